// round 1
// baseline (speedup 1.0000x reference)
#include <cuda_runtime.h>
#include <cstdint>

// ---------------------------------------------------------------------------
// DistancePredictor: out[b,i,j,n] = relu(xi[b,i,:] * xj[b,j,:]) @ Wo[:,n] + bo[n]
//   xi = x@Wi + bi, xj = x@Wj + bj
// B=2, L=384, D=1280, H=256, NB=10
// ---------------------------------------------------------------------------

#define B_   2
#define L_   384
#define D_   1280
#define H_   256
#define NB_  10
#define ROWS_ (B_ * L_)   // 768

// Scratch for projections (device globals: no allocation allowed)
__device__ float g_xi[ROWS_ * H_];
__device__ float g_xj[ROWS_ * H_];

// ---- packed f32x2 helpers (sm_100+ PTX) -----------------------------------
typedef unsigned long long u64;

__device__ __forceinline__ u64 pk2(float a, float b) {
    u64 r;
    asm("mov.b64 %0, {%1, %2};"
        : "=l"(r) : "r"(__float_as_uint(a)), "r"(__float_as_uint(b)));
    return r;
}
__device__ __forceinline__ void fma2(u64& d, u64 a, u64 b) {
    asm("fma.rn.f32x2 %0, %1, %2, %0;" : "+l"(d) : "l"(a), "l"(b));
}
__device__ __forceinline__ u64 add2(u64 a, u64 b) {
    u64 d;
    asm("add.rn.f32x2 %0, %1, %2;" : "=l"(d) : "l"(a), "l"(b));
    return d;
}

// ---------------------------------------------------------------------------
// Stage 1: C[768,256] = X[768,1280] @ W[1280,256] + bias   (W = Wi or Wj)
// BM=64, BN=64, BK=16, 256 threads (16x16), 4x4 per thread, f32x2 accum.
// ---------------------------------------------------------------------------
__global__ __launch_bounds__(256) void proj_kernel(
    const float* __restrict__ X,
    const float* __restrict__ Wi, const float* __restrict__ bi,
    const float* __restrict__ Wj, const float* __restrict__ bj)
{
    const float* W    = (blockIdx.z == 0) ? Wi : Wj;
    const float* bias = (blockIdx.z == 0) ? bi : bj;
    float*       C    = (blockIdx.z == 0) ? g_xi : g_xj;

    __shared__ float As[16][68];   // [k][m], +4 pad keeps 16B row alignment
    __shared__ float Bs[16][64];   // [k][n]

    const int tid = threadIdx.x;
    const int tx  = tid & 15;      // col group
    const int ty  = tid >> 4;      // row group
    const int m0  = blockIdx.y * 64;
    const int n0  = blockIdx.x * 64;

    // A loader: X[m0+a_m][k0 + a_k4 .. +3]  (coalesced along k)
    const int a_m  = tid >> 2;         // 0..63
    const int a_k4 = (tid & 3) << 2;   // 0,4,8,12
    // B loader: W[k0+b_k][n0 + b_n4 .. +3] (coalesced along n)
    const int b_k  = tid >> 4;         // 0..15
    const int b_n4 = (tid & 15) << 2;

    u64 acc2[4][2];
    #pragma unroll
    for (int r = 0; r < 4; r++) { acc2[r][0] = 0ull; acc2[r][1] = 0ull; }

    for (int k0 = 0; k0 < D_; k0 += 16) {
        float4 av = *(const float4*)&X[(m0 + a_m) * D_ + k0 + a_k4];
        float4 bv = *(const float4*)&W[(k0 + b_k) * H_ + n0 + b_n4];
        __syncthreads();
        As[a_k4 + 0][a_m] = av.x;
        As[a_k4 + 1][a_m] = av.y;
        As[a_k4 + 2][a_m] = av.z;
        As[a_k4 + 3][a_m] = av.w;
        *(float4*)&Bs[b_k][b_n4] = bv;
        __syncthreads();

        #pragma unroll
        for (int kk = 0; kk < 16; kk++) {
            float4 a4 = *(const float4*)&As[kk][ty << 2];
            float4 b4 = *(const float4*)&Bs[kk][tx << 2];
            u64 b2lo = pk2(b4.x, b4.y);
            u64 b2hi = pk2(b4.z, b4.w);
            float ar[4] = {a4.x, a4.y, a4.z, a4.w};
            #pragma unroll
            for (int r = 0; r < 4; r++) {
                u64 a2 = pk2(ar[r], ar[r]);
                fma2(acc2[r][0], a2, b2lo);
                fma2(acc2[r][1], a2, b2hi);
            }
        }
    }

    // epilogue: add bias, store as 8B packed
    const int ncol = n0 + (tx << 2);
    u64 bia0 = pk2(bias[ncol + 0], bias[ncol + 1]);
    u64 bia1 = pk2(bias[ncol + 2], bias[ncol + 3]);
    #pragma unroll
    for (int r = 0; r < 4; r++) {
        int row = m0 + (ty << 2) + r;
        u64 v0 = add2(acc2[r][0], bia0);
        u64 v1 = add2(acc2[r][1], bia1);
        *(u64*)&C[row * H_ + ncol + 0] = v0;
        *(u64*)&C[row * H_ + ncol + 2] = v1;
    }
}

// ---------------------------------------------------------------------------
// Stage 2: out[b,i,j,0:10] = sum_h relu(xi[b,i,h]*xj[b,j,h]) * Wo[h,0:10] + bo
// Block: 8 i's (1 per warp) x 128 j's (4 per lane). h processed in 8 chunks
// of 32 with Xj transposed into smem. 10 outputs packed as 5 f32x2 accums.
// ---------------------------------------------------------------------------
__global__ __launch_bounds__(256) void pair_kernel(
    const float* __restrict__ Wo, const float* __restrict__ bo,
    float* __restrict__ out)
{
    __shared__ float Xi_s[8][H_];       // 8 KB
    __shared__ float Wo_s[H_ * NB_];    // 10.24 KB  [h*10+n]
    __shared__ float XjT[32][128];      // 16 KB     [h_local][j_local]

    const int tid  = threadIdx.x;
    const int w    = tid >> 5;          // warp = i within tile
    const int lane = tid & 31;
    const int b    = blockIdx.z;
    const int i    = blockIdx.y * 8 + w;
    const int j0   = blockIdx.x * 128;

    // Load this block's 8 Xi rows (all 256 h)
    for (int q = tid; q < 8 * 64; q += 256) {      // q indexes float4
        int row = q >> 6, c4 = (q & 63) << 2;
        *(float4*)&Xi_s[row][c4] =
            *(const float4*)&g_xi[(b * L_ + blockIdx.y * 8 + row) * H_ + c4];
    }
    // Load full Wo
    for (int q = tid; q < H_ * NB_; q += 256) Wo_s[q] = Wo[q];

    // bo packed into registers
    u64 bo2[5];
    #pragma unroll
    for (int c = 0; c < 5; c++) bo2[c] = pk2(bo[2 * c], bo[2 * c + 1]);

    u64 acc2[4][5];
    #pragma unroll
    for (int jj = 0; jj < 4; jj++)
        #pragma unroll
        for (int c = 0; c < 5; c++) acc2[jj][c] = 0ull;

    const int jl_ld   = tid >> 1;            // 0..127
    const int hoff_ld = (tid & 1) << 4;      // 0 or 16

    for (int ch = 0; ch < 8; ch++) {
        __syncthreads();
        // Transpose-load a 128j x 32h chunk of Xj into XjT[h][j]
        {
            const float* src = &g_xj[(b * L_ + j0 + jl_ld) * H_ + ch * 32 + hoff_ld];
            #pragma unroll
            for (int q = 0; q < 4; q++) {
                float4 v = *(const float4*)&src[q * 4];
                XjT[hoff_ld + q * 4 + 0][jl_ld] = v.x;
                XjT[hoff_ld + q * 4 + 1][jl_ld] = v.y;
                XjT[hoff_ld + q * 4 + 2][jl_ld] = v.z;
                XjT[hoff_ld + q * 4 + 3][jl_ld] = v.w;
            }
        }
        __syncthreads();

        #pragma unroll
        for (int hh = 0; hh < 32; hh++) {
            const int hg = ch * 32 + hh;
            float  xi  = Xi_s[w][hg];
            float4 xj  = *(const float4*)&XjT[hh][lane << 2];

            float p0 = fmaxf(xi * xj.x, 0.0f);
            float p1 = fmaxf(xi * xj.y, 0.0f);
            float p2v = fmaxf(xi * xj.z, 0.0f);
            float p3 = fmaxf(xi * xj.w, 0.0f);
            u64 pp[4];
            pp[0] = pk2(p0, p0);
            pp[1] = pk2(p1, p1);
            pp[2] = pk2(p2v, p2v);
            pp[3] = pk2(p3, p3);

            const float* wrow = &Wo_s[hg * NB_];
            #pragma unroll
            for (int c = 0; c < 5; c++) {
                u64 wo2 = *(const u64*)&wrow[2 * c];   // 8B-aligned (40h+8c)
                fma2(acc2[0][c], pp[0], wo2);
                fma2(acc2[1][c], pp[1], wo2);
                fma2(acc2[2][c], pp[2], wo2);
                fma2(acc2[3][c], pp[3], wo2);
            }
        }
    }

    // Epilogue: add bo, store 10 floats per (i,j) as 5x 8B stores
    const int jbase = j0 + (lane << 2);
    long long base = ((long long)(b * L_ + i) * L_ + jbase) * NB_;
    #pragma unroll
    for (int jj = 0; jj < 4; jj++) {
        #pragma unroll
        for (int c = 0; c < 5; c++) {
            u64 v = add2(acc2[jj][c], bo2[c]);
            *(u64*)&out[base + jj * NB_ + 2 * c] = v;
        }
    }
}

// ---------------------------------------------------------------------------
extern "C" void kernel_launch(void* const* d_in, const int* in_sizes, int n_in,
                              void* d_out, int out_size)
{
    const float* x  = (const float*)d_in[0];
    const float* Wi = (const float*)d_in[1];
    const float* bi = (const float*)d_in[2];
    const float* Wj = (const float*)d_in[3];
    const float* bj = (const float*)d_in[4];
    const float* Wo = (const float*)d_in[5];
    const float* bo = (const float*)d_in[6];
    float* out = (float*)d_out;

    proj_kernel<<<dim3(H_ / 64, ROWS_ / 64, 2), 256>>>(x, Wi, bi, Wj, bj);
    pair_kernel<<<dim3(L_ / 128, L_ / 8, B_), 256>>>(Wo, bo, out);
}

// round 2
// speedup vs baseline: 1.0012x; 1.0012x over previous
#include <cuda_runtime.h>
#include <cstdint>

// ---------------------------------------------------------------------------
// DistancePredictor: out[b,i,j,n] = relu(xi[b,i,:] * xj[b,j,:]) @ Wo[:,n] + bo[n]
//   xi = x@Wi + bi, xj = x@Wj + bj
// B=2, L=384, D=1280, H=256, NB=10
// ---------------------------------------------------------------------------

#define B_   2
#define L_   384
#define D_   1280
#define H_   256
#define NB_  10
#define ROWS_ (B_ * L_)   // 768

// Scratch for projections (device globals: no allocation allowed)
__device__ float g_xi[ROWS_ * H_];
__device__ float g_xj[ROWS_ * H_];

// ---- packed f32x2 helpers (sm_100+ PTX) -----------------------------------
typedef unsigned long long u64;

__device__ __forceinline__ u64 pk2(float a, float b) {
    u64 r;
    asm("mov.b64 %0, {%1, %2};"
        : "=l"(r) : "r"(__float_as_uint(a)), "r"(__float_as_uint(b)));
    return r;
}
__device__ __forceinline__ void fma2(u64& d, u64 a, u64 b) {
    asm("fma.rn.f32x2 %0, %1, %2, %0;" : "+l"(d) : "l"(a), "l"(b));
}
__device__ __forceinline__ u64 add2(u64 a, u64 b) {
    u64 d;
    asm("add.rn.f32x2 %0, %1, %2;" : "=l"(d) : "l"(a), "l"(b));
    return d;
}

// ---------------------------------------------------------------------------
// Stage 1: C[768,256] = X[768,1280] @ W[1280,256] + bias   (W = Wi or Wj)
// BM=64, BN=64, BK=16, 256 threads (16x16), 4x4 per thread, f32x2 accum.
// ---------------------------------------------------------------------------
__global__ __launch_bounds__(256) void proj_kernel(
    const float* __restrict__ X,
    const float* __restrict__ Wi, const float* __restrict__ bi,
    const float* __restrict__ Wj, const float* __restrict__ bj)
{
    const float* W    = (blockIdx.z == 0) ? Wi : Wj;
    const float* bias = (blockIdx.z == 0) ? bi : bj;
    float*       C    = (blockIdx.z == 0) ? g_xi : g_xj;

    __shared__ float As[16][68];   // [k][m], +4 pad keeps 16B row alignment
    __shared__ float Bs[16][64];   // [k][n]

    const int tid = threadIdx.x;
    const int tx  = tid & 15;      // col group
    const int ty  = tid >> 4;      // row group
    const int m0  = blockIdx.y * 64;
    const int n0  = blockIdx.x * 64;

    // A loader: X[m0+a_m][k0 + a_k4 .. +3]  (coalesced along k)
    const int a_m  = tid >> 2;         // 0..63
    const int a_k4 = (tid & 3) << 2;   // 0,4,8,12
    // B loader: W[k0+b_k][n0 + b_n4 .. +3] (coalesced along n)
    const int b_k  = tid >> 4;         // 0..15
    const int b_n4 = (tid & 15) << 2;

    u64 acc2[4][2];
    #pragma unroll
    for (int r = 0; r < 4; r++) { acc2[r][0] = 0ull; acc2[r][1] = 0ull; }

    for (int k0 = 0; k0 < D_; k0 += 16) {
        float4 av = *(const float4*)&X[(m0 + a_m) * D_ + k0 + a_k4];
        float4 bv = *(const float4*)&W[(k0 + b_k) * H_ + n0 + b_n4];
        __syncthreads();
        As[a_k4 + 0][a_m] = av.x;
        As[a_k4 + 1][a_m] = av.y;
        As[a_k4 + 2][a_m] = av.z;
        As[a_k4 + 3][a_m] = av.w;
        *(float4*)&Bs[b_k][b_n4] = bv;
        __syncthreads();

        #pragma unroll
        for (int kk = 0; kk < 16; kk++) {
            float4 a4 = *(const float4*)&As[kk][ty << 2];
            float4 b4 = *(const float4*)&Bs[kk][tx << 2];
            u64 b2lo = pk2(b4.x, b4.y);
            u64 b2hi = pk2(b4.z, b4.w);
            float ar[4] = {a4.x, a4.y, a4.z, a4.w};
            #pragma unroll
            for (int r = 0; r < 4; r++) {
                u64 a2 = pk2(ar[r], ar[r]);
                fma2(acc2[r][0], a2, b2lo);
                fma2(acc2[r][1], a2, b2hi);
            }
        }
    }

    // epilogue: add bias, store as 8B packed
    const int ncol = n0 + (tx << 2);
    u64 bia0 = pk2(bias[ncol + 0], bias[ncol + 1]);
    u64 bia1 = pk2(bias[ncol + 2], bias[ncol + 3]);
    #pragma unroll
    for (int r = 0; r < 4; r++) {
        int row = m0 + (ty << 2) + r;
        u64 v0 = add2(acc2[r][0], bia0);
        u64 v1 = add2(acc2[r][1], bia1);
        *(u64*)&C[row * H_ + ncol + 0] = v0;
        *(u64*)&C[row * H_ + ncol + 2] = v1;
    }
}

// ---------------------------------------------------------------------------
// Stage 2: out[b,i,j,0:10] = sum_h relu(xi[b,i,h]*xj[b,j,h]) * Wo[h,0:10] + bo
// Block: 8 i's (1 per warp) x 128 j's (4 per lane). h processed in 8 chunks
// of 32 with Xj transposed into smem. 10 outputs packed as 5 f32x2 accums.
// ---------------------------------------------------------------------------
__global__ __launch_bounds__(256) void pair_kernel(
    const float* __restrict__ Wo, const float* __restrict__ bo,
    float* __restrict__ out)
{
    __shared__ float Xi_s[8][H_];       // 8 KB
    __shared__ float Wo_s[H_ * NB_];    // 10.24 KB  [h*10+n]
    __shared__ float XjT[32][128];      // 16 KB     [h_local][j_local]

    const int tid  = threadIdx.x;
    const int w    = tid >> 5;          // warp = i within tile
    const int lane = tid & 31;
    const int b    = blockIdx.z;
    const int i    = blockIdx.y * 8 + w;
    const int j0   = blockIdx.x * 128;

    // Load this block's 8 Xi rows (all 256 h)
    for (int q = tid; q < 8 * 64; q += 256) {      // q indexes float4
        int row = q >> 6, c4 = (q & 63) << 2;
        *(float4*)&Xi_s[row][c4] =
            *(const float4*)&g_xi[(b * L_ + blockIdx.y * 8 + row) * H_ + c4];
    }
    // Load full Wo
    for (int q = tid; q < H_ * NB_; q += 256) Wo_s[q] = Wo[q];

    // bo packed into registers
    u64 bo2[5];
    #pragma unroll
    for (int c = 0; c < 5; c++) bo2[c] = pk2(bo[2 * c], bo[2 * c + 1]);

    u64 acc2[4][5];
    #pragma unroll
    for (int jj = 0; jj < 4; jj++)
        #pragma unroll
        for (int c = 0; c < 5; c++) acc2[jj][c] = 0ull;

    const int jl_ld   = tid >> 1;            // 0..127
    const int hoff_ld = (tid & 1) << 4;      // 0 or 16

    for (int ch = 0; ch < 8; ch++) {
        __syncthreads();
        // Transpose-load a 128j x 32h chunk of Xj into XjT[h][j]
        {
            const float* src = &g_xj[(b * L_ + j0 + jl_ld) * H_ + ch * 32 + hoff_ld];
            #pragma unroll
            for (int q = 0; q < 4; q++) {
                float4 v = *(const float4*)&src[q * 4];
                XjT[hoff_ld + q * 4 + 0][jl_ld] = v.x;
                XjT[hoff_ld + q * 4 + 1][jl_ld] = v.y;
                XjT[hoff_ld + q * 4 + 2][jl_ld] = v.z;
                XjT[hoff_ld + q * 4 + 3][jl_ld] = v.w;
            }
        }
        __syncthreads();

        #pragma unroll
        for (int hh = 0; hh < 32; hh++) {
            const int hg = ch * 32 + hh;
            float  xi  = Xi_s[w][hg];
            float4 xj  = *(const float4*)&XjT[hh][lane << 2];

            float p0 = fmaxf(xi * xj.x, 0.0f);
            float p1 = fmaxf(xi * xj.y, 0.0f);
            float p2v = fmaxf(xi * xj.z, 0.0f);
            float p3 = fmaxf(xi * xj.w, 0.0f);
            u64 pp[4];
            pp[0] = pk2(p0, p0);
            pp[1] = pk2(p1, p1);
            pp[2] = pk2(p2v, p2v);
            pp[3] = pk2(p3, p3);

            const float* wrow = &Wo_s[hg * NB_];
            #pragma unroll
            for (int c = 0; c < 5; c++) {
                u64 wo2 = *(const u64*)&wrow[2 * c];   // 8B-aligned (40h+8c)
                fma2(acc2[0][c], pp[0], wo2);
                fma2(acc2[1][c], pp[1], wo2);
                fma2(acc2[2][c], pp[2], wo2);
                fma2(acc2[3][c], pp[3], wo2);
            }
        }
    }

    // Epilogue: add bo, store 10 floats per (i,j) as 5x 8B stores
    const int jbase = j0 + (lane << 2);
    long long base = ((long long)(b * L_ + i) * L_ + jbase) * NB_;
    #pragma unroll
    for (int jj = 0; jj < 4; jj++) {
        #pragma unroll
        for (int c = 0; c < 5; c++) {
            u64 v = add2(acc2[jj][c], bo2[c]);
            *(u64*)&out[base + jj * NB_ + 2 * c] = v;
        }
    }
}

// ---------------------------------------------------------------------------
extern "C" void kernel_launch(void* const* d_in, const int* in_sizes, int n_in,
                              void* d_out, int out_size)
{
    const float* x  = (const float*)d_in[0];
    const float* Wi = (const float*)d_in[1];
    const float* bi = (const float*)d_in[2];
    const float* Wj = (const float*)d_in[3];
    const float* bj = (const float*)d_in[4];
    const float* Wo = (const float*)d_in[5];
    const float* bo = (const float*)d_in[6];
    float* out = (float*)d_out;

    proj_kernel<<<dim3(H_ / 64, ROWS_ / 64, 2), 256>>>(x, Wi, bi, Wj, bj);
    pair_kernel<<<dim3(L_ / 128, L_ / 8, B_), 256>>>(Wo, bo, out);
}

// round 3
// speedup vs baseline: 1.3328x; 1.3312x over previous
#include <cuda_runtime.h>
#include <cstdint>

// ---------------------------------------------------------------------------
// DistancePredictor: out[b,i,j,n] = relu(xi[b,i,:]*xj[b,j,:]) @ Wo[:,n] + bo[n]
//   xi = x@Wi + bi, xj = x@Wj + bj
// B=2, L=384, D=1280, H=256, NB=10
// ---------------------------------------------------------------------------

#define B_   2
#define L_   384
#define D_   1280
#define H_   256
#define NB_  10
#define ROWS_ (B_ * L_)   // 768
#define SPLITK_ 4
#define KCH_ (D_ / SPLITK_)   // 320

// Device scratch (no allocation allowed)
__device__ __align__(16) float g_xi[ROWS_ * H_];
__device__ __align__(16) float g_xj[ROWS_ * H_];
__device__ __align__(16) float g_part[2 * SPLITK_ * ROWS_ * H_];  // 6 MB

// ---- packed f32x2 helpers (sm_100+) ---------------------------------------
typedef unsigned long long u64;

__device__ __forceinline__ u64 pk2(float a, float b) {
    u64 r;
    asm("mov.b64 %0, {%1, %2};"
        : "=l"(r) : "r"(__float_as_uint(a)), "r"(__float_as_uint(b)));
    return r;
}
__device__ __forceinline__ void fma2(u64& d, u64 a, u64 b) {
    asm("fma.rn.f32x2 %0, %1, %2, %0;" : "+l"(d) : "l"(a), "l"(b));
}
__device__ __forceinline__ u64 add2(u64 a, u64 b) {
    u64 d;
    asm("add.rn.f32x2 %0, %1, %2;" : "=l"(d) : "l"(a), "l"(b));
    return d;
}

// ---------------------------------------------------------------------------
// Stage 1: partial GEMM. grid (4, 12, 8): x = n-tile(64), y = m-tile(64),
// z = split(0..3) | proj(<<2). 64 threads, 8x8 per thread, BK=16.
// Writes g_part[(proj*4+split)][row][h].
// ---------------------------------------------------------------------------
__global__ __launch_bounds__(64) void proj_kernel(
    const float* __restrict__ X,
    const float* __restrict__ Wi, const float* __restrict__ Wj)
{
    const int split = blockIdx.z & 3;
    const int pj    = blockIdx.z >> 2;
    const float* W  = pj ? Wj : Wi;
    float* P = g_part + (size_t)(pj * SPLITK_ + split) * ROWS_ * H_;

    __shared__ __align__(16) float As[16][68];   // [k][m]
    __shared__ __align__(16) float Bs[16][68];   // [k][n]

    const int tid = threadIdx.x;
    const int tx  = tid & 7;        // n group (8 cols)
    const int ty  = tid >> 3;       // m group (8 rows)
    const int m0  = blockIdx.y * 64;
    const int n0  = blockIdx.x * 64;
    const int kb  = split * KCH_;

    u64 acc[8][4];
    #pragma unroll
    for (int r = 0; r < 8; r++)
        #pragma unroll
        for (int c = 0; c < 4; c++) acc[r][c] = 0ull;

    const int a_row = tid >> 2;           // 0..15 (+16p)
    const int a_k4  = (tid & 3) << 2;     // 0,4,8,12
    const int b_k   = tid >> 4;           // 0..3 (+4p)
    const int b_n4  = (tid & 15) << 2;    // 0..60

    for (int k0 = 0; k0 < KCH_; k0 += 16) {
        // stage global loads in registers
        float4 av[4], bv[4];
        #pragma unroll
        for (int p = 0; p < 4; p++)
            av[p] = *(const float4*)&X[(m0 + a_row + p * 16) * D_ + kb + k0 + a_k4];
        #pragma unroll
        for (int p = 0; p < 4; p++)
            bv[p] = *(const float4*)&W[(kb + k0 + b_k + p * 4) * H_ + n0 + b_n4];

        __syncthreads();
        #pragma unroll
        for (int p = 0; p < 4; p++) {
            int row = a_row + p * 16;
            As[a_k4 + 0][row] = av[p].x;
            As[a_k4 + 1][row] = av[p].y;
            As[a_k4 + 2][row] = av[p].z;
            As[a_k4 + 3][row] = av[p].w;
            *(float4*)&Bs[b_k + p * 4][b_n4] = bv[p];
        }
        __syncthreads();

        #pragma unroll
        for (int kk = 0; kk < 16; kk++) {
            float4 a0 = *(const float4*)&As[kk][ty << 3];
            float4 a1 = *(const float4*)&As[kk][(ty << 3) + 4];
            float4 b0 = *(const float4*)&Bs[kk][tx << 3];
            float4 b1 = *(const float4*)&Bs[kk][(tx << 3) + 4];
            u64 b2[4] = { pk2(b0.x, b0.y), pk2(b0.z, b0.w),
                          pk2(b1.x, b1.y), pk2(b1.z, b1.w) };
            float aval[8] = { a0.x, a0.y, a0.z, a0.w, a1.x, a1.y, a1.z, a1.w };
            #pragma unroll
            for (int r = 0; r < 8; r++) {
                u64 ad = pk2(aval[r], aval[r]);
                #pragma unroll
                for (int c = 0; c < 4; c++) fma2(acc[r][c], ad, b2[c]);
            }
        }
    }

    // epilogue: raw partials
    #pragma unroll
    for (int r = 0; r < 8; r++) {
        float* dst = &P[(m0 + (ty << 3) + r) * H_ + n0 + (tx << 3)];
        *(u64*)&dst[0] = acc[r][0];
        *(u64*)&dst[2] = acc[r][1];
        *(u64*)&dst[4] = acc[r][2];
        *(u64*)&dst[6] = acc[r][3];
    }
}

// ---------------------------------------------------------------------------
// Stage 1b: reduce the 4 split-K partials + bias -> g_xi / g_xj
// grid (192, 2), 256 threads; each thread one float4.
// ---------------------------------------------------------------------------
__global__ __launch_bounds__(256) void reduce_kernel(
    const float* __restrict__ bi, const float* __restrict__ bj)
{
    const int pj = blockIdx.y;
    const int q  = blockIdx.x * 256 + threadIdx.x;   // 0..49151
    const int flat = q << 2;                          // float index

    const float* base = g_part + (size_t)pj * SPLITK_ * ROWS_ * H_;
    float4 s = *(const float4*)&base[flat];
    #pragma unroll
    for (int sp = 1; sp < SPLITK_; sp++) {
        float4 v = *(const float4*)&base[sp * ROWS_ * H_ + flat];
        s.x += v.x; s.y += v.y; s.z += v.z; s.w += v.w;
    }
    const float* bias = pj ? bj : bi;
    float4 bv = *(const float4*)&bias[flat & (H_ - 1)];
    s.x += bv.x; s.y += bv.y; s.z += bv.z; s.w += bv.w;

    float* dst = pj ? g_xj : g_xi;
    *(float4*)&dst[flat] = s;
}

// ---------------------------------------------------------------------------
// Stage 2: out[b,i,j,0:10] = sum_h relu(xi[i,h]*xj[j,h]) * Wo[h,:] + bo
// Block 256 thr = 8 warps; warp w handles i pair (2w, 2w+1) x 128 j.
// Block tile: 16 i x 128 j. Grid (3, 24, 2) = 144 blocks (one wave).
// ---------------------------------------------------------------------------
__global__ __launch_bounds__(256) void pair_kernel(
    const float* __restrict__ Wo, const float* __restrict__ bo,
    float* __restrict__ out)
{
    __shared__ __align__(16) float XiT[H_][18];     // [h][i_local], pad 2 -> 18 KB
    __shared__ __align__(16) float Wo_s[H_ * NB_];  // 10 KB
    __shared__ __align__(16) float XjT[32][128];    // [h_loc][j_local], 16 KB

    const int tid  = threadIdx.x;
    const int w    = tid >> 5;
    const int lane = tid & 31;
    const int b    = blockIdx.z;
    const int i0   = blockIdx.y * 16;
    const int j0   = blockIdx.x * 128;

    // Fill XiT transposed: il = tid>>4, h = (tid&15)*4 + p*64
    {
        const int il = tid >> 4;
        const int hb = (tid & 15) << 2;
        const float* src = &g_xi[(b * L_ + i0 + il) * H_];
        #pragma unroll
        for (int p = 0; p < 4; p++) {
            int h = hb + p * 64;
            float4 v = *(const float4*)&src[h];
            XiT[h + 0][il] = v.x;
            XiT[h + 1][il] = v.y;
            XiT[h + 2][il] = v.z;
            XiT[h + 3][il] = v.w;
        }
    }
    for (int q = tid; q < H_ * NB_; q += 256) Wo_s[q] = Wo[q];

    u64 bo2[5];
    #pragma unroll
    for (int c = 0; c < 5; c++) bo2[c] = pk2(bo[2 * c], bo[2 * c + 1]);

    u64 acc[2][4][5];
    #pragma unroll
    for (int ii = 0; ii < 2; ii++)
        #pragma unroll
        for (int jj = 0; jj < 4; jj++)
            #pragma unroll
            for (int c = 0; c < 5; c++) acc[ii][jj][c] = 0ull;

    const int jl  = tid >> 1;            // 0..127
    const int hof = (tid & 1) << 4;      // 0 or 16
    const float* xjsrc = &g_xj[(b * L_ + j0 + jl) * H_];

    for (int ch = 0; ch < 8; ch++) {
        __syncthreads();
        #pragma unroll
        for (int q = 0; q < 4; q++) {
            float4 v = *(const float4*)&xjsrc[ch * 32 + hof + q * 4];
            XjT[hof + q * 4 + 0][jl] = v.x;
            XjT[hof + q * 4 + 1][jl] = v.y;
            XjT[hof + q * 4 + 2][jl] = v.z;
            XjT[hof + q * 4 + 3][jl] = v.w;
        }
        __syncthreads();

        #pragma unroll
        for (int hh = 0; hh < 32; hh++) {
            const int hg = ch * 32 + hh;
            float2 xi = *(const float2*)&XiT[hg][w << 1];   // (xi_a, xi_b) bcast
            float4 xj = *(const float4*)&XjT[hh][lane << 2];

            float pa0 = fmaxf(xi.x * xj.x, 0.0f);
            float pa1 = fmaxf(xi.x * xj.y, 0.0f);
            float pa2 = fmaxf(xi.x * xj.z, 0.0f);
            float pa3 = fmaxf(xi.x * xj.w, 0.0f);
            float pb0 = fmaxf(xi.y * xj.x, 0.0f);
            float pb1 = fmaxf(xi.y * xj.y, 0.0f);
            float pb2 = fmaxf(xi.y * xj.z, 0.0f);
            float pb3 = fmaxf(xi.y * xj.w, 0.0f);
            u64 pa[4] = { pk2(pa0, pa0), pk2(pa1, pa1), pk2(pa2, pa2), pk2(pa3, pa3) };
            u64 pb[4] = { pk2(pb0, pb0), pk2(pb1, pb1), pk2(pb2, pb2), pk2(pb3, pb3) };

            const float* wr = &Wo_s[hg * NB_];
            #pragma unroll
            for (int c = 0; c < 5; c++) {
                u64 wo2 = *(const u64*)&wr[2 * c];
                fma2(acc[0][0][c], pa[0], wo2);
                fma2(acc[0][1][c], pa[1], wo2);
                fma2(acc[0][2][c], pa[2], wo2);
                fma2(acc[0][3][c], pa[3], wo2);
                fma2(acc[1][0][c], pb[0], wo2);
                fma2(acc[1][1][c], pb[1], wo2);
                fma2(acc[1][2][c], pb[2], wo2);
                fma2(acc[1][3][c], pb[3], wo2);
            }
        }
    }

    // Epilogue
    #pragma unroll
    for (int ii = 0; ii < 2; ii++) {
        const int i = i0 + (w << 1) + ii;
        size_t base = ((size_t)(b * L_ + i) * L_ + j0 + (lane << 2)) * NB_;
        #pragma unroll
        for (int jj = 0; jj < 4; jj++) {
            #pragma unroll
            for (int c = 0; c < 5; c++) {
                u64 v = add2(acc[ii][jj][c], bo2[c]);
                *(u64*)&out[base + jj * NB_ + 2 * c] = v;
            }
        }
    }
}

// ---------------------------------------------------------------------------
extern "C" void kernel_launch(void* const* d_in, const int* in_sizes, int n_in,
                              void* d_out, int out_size)
{
    const float* x  = (const float*)d_in[0];
    const float* Wi = (const float*)d_in[1];
    const float* bi = (const float*)d_in[2];
    const float* Wj = (const float*)d_in[3];
    const float* bj = (const float*)d_in[4];
    const float* Wo = (const float*)d_in[5];
    const float* bo = (const float*)d_in[6];
    float* out = (float*)d_out;

    proj_kernel<<<dim3(H_ / 64, ROWS_ / 64, SPLITK_ * 2), 64>>>(x, Wi, Wj);
    reduce_kernel<<<dim3(192, 2), 256>>>(bi, bj);
    pair_kernel<<<dim3(L_ / 128, L_ / 16, B_), 256>>>(Wo, bo, out);
}